// round 10
// baseline (speedup 1.0000x reference)
#include <cuda_runtime.h>
#include <cstdint>

#define NN 50000
#define FIN 128
#define HC  128          // H*C = 4*32
#define EE  800000
#define ET  850000       // EE + NN self loops
#define NEG_SLOPE 0.2f

// ---- scratch (static device globals; no runtime allocation) ----
__device__ float g_xl[NN * HC];      // x @ Wl
__device__ float g_xr[NN * HC];      // x @ Wr
__device__ int   g_deg[NN];
__device__ int   g_cur[NN];
__device__ int   g_off[NN + 1];
__device__ int   g_ssrc[ET];         // src node per CSR slot
__device__ int   g_seid[ET];         // original edge id per CSR slot
__device__ int   g_is64;             // edge_index dtype flag
__device__ float g_logit[ET * 4];    // per-edge per-head raw attention logit
__device__ float g_sm[NN * 4];       // per-dst per-head softmax max
__device__ float g_sinv[NN * 4];     // per-dst per-head 1/denominator
__device__ int   g_bsum[64];         // block sums for scan
__device__ int   g_bsum_ex[65];      // exclusive-scanned block sums

// ---- probe: detect int64 vs int32 edge_index (parallel, 64 samples) ----
__global__ void probe_kernel(const int* __restrict__ ei32) {
    __shared__ int nz;
    if (threadIdx.x == 0) nz = 0;
    __syncthreads();
    if (threadIdx.x < 64) {
        long long k = ((long long)threadIdx.x * 1234567) % EE;
        int idx = (int)(2 * k + 1);                    // high word if int64
        if (ei32[idx] != 0) atomicAdd(&nz, 1);
    }
    __syncthreads();
    if (threadIdx.x == 0) g_is64 = (nz == 0) ? 1 : 0;
}

__device__ __forceinline__ void load_edge(const void* ei, int e, int& src, int& dst) {
    if (e >= EE) { src = dst = e - EE; return; }
    if (g_is64) {
        const long long* p = (const long long*)ei;
        src = (int)p[e]; dst = (int)p[EE + e];
    } else {
        const int* p = (const int*)ei;
        src = p[e]; dst = p[EE + e];
    }
    src = min(max(src, 0), NN - 1);
    dst = min(max(dst, 0), NN - 1);
}

__global__ void zero_kernel() {
    int i = blockIdx.x * blockDim.x + threadIdx.x;
    if (i < NN) { g_deg[i] = 0; g_cur[i] = 0; }
}

// ==================================================================
// Fused 3xTF32 tensor-core GEMM: [NN,128] @ [128, 128|128] -> g_xl,g_xr
// ==================================================================
#define LDA 20   // 16 + 4 pad
#define LDB 264  // 256 + 8 pad

__device__ __forceinline__ uint32_t f2tf(float f) {
    uint32_t u;
    asm("cvt.rna.tf32.f32 %0, %1;" : "=r"(u) : "f"(f));
    return u;
}
__device__ __forceinline__ void split_tf(float v, uint32_t& hi, uint32_t& lo) {
    hi = f2tf(v);
    lo = f2tf(v - __uint_as_float(hi));
}
__device__ __forceinline__ void mma_tf32(float* c, const uint32_t* a, const uint32_t* b) {
    asm volatile(
        "mma.sync.aligned.m16n8k8.row.col.f32.tf32.tf32.f32 "
        "{%0,%1,%2,%3},{%4,%5,%6,%7},{%8,%9},{%0,%1,%2,%3};"
        : "+f"(c[0]), "+f"(c[1]), "+f"(c[2]), "+f"(c[3])
        : "r"(a[0]), "r"(a[1]), "r"(a[2]), "r"(a[3]), "r"(b[0]), "r"(b[1]));
}

__global__ __launch_bounds__(512, 1)
void gemm_fused_kernel(const float* __restrict__ x,
                       const float* __restrict__ Wl,
                       const float* __restrict__ Wr) {
    __shared__ float As[128 * LDA];
    __shared__ float Bs[16 * LDB];

    int tid  = threadIdx.x;
    int wid  = tid >> 5;
    int lane = tid & 31;
    int wm   = wid & 3;
    int wn   = wid >> 2;
    int g    = lane >> 2;
    int t4   = lane & 3;
    int row0 = blockIdx.x * 128;

    float acc[2][8][4];
#pragma unroll
    for (int mt = 0; mt < 2; mt++)
#pragma unroll
        for (int nt = 0; nt < 8; nt++)
#pragma unroll
            for (int i = 0; i < 4; i++) acc[mt][nt][i] = 0.f;

    for (int kc = 0; kc < 8; kc++) {
        {
            int r = tid >> 2, c4 = tid & 3;
            int rr = row0 + r; if (rr >= NN) rr = NN - 1;
            float4 v = *(const float4*)&x[rr * FIN + kc * 16 + c4 * 4];
            *(float4*)&As[r * LDA + c4 * 4] = v;
        }
#pragma unroll
        for (int i = 0; i < 2; i++) {
            int idx = i * 512 + tid;
            int r = idx >> 6, c4 = idx & 63;
            int col = c4 * 4;
            const float* Wp = (col < 128) ? &Wl[(kc * 16 + r) * HC + col]
                                          : &Wr[(kc * 16 + r) * HC + col - 128];
            *(float4*)&Bs[r * LDB + col] = *(const float4*)Wp;
        }
        __syncthreads();

#pragma unroll
        for (int ks = 0; ks < 2; ks++) {
            uint32_t ah[2][4], al[2][4];
#pragma unroll
            for (int mt = 0; mt < 2; mt++) {
                int rb = wm * 32 + mt * 16 + g;
                int kb = ks * 8 + t4;
                split_tf(As[rb * LDA + kb],           ah[mt][0], al[mt][0]);
                split_tf(As[(rb + 8) * LDA + kb],     ah[mt][1], al[mt][1]);
                split_tf(As[rb * LDA + kb + 4],       ah[mt][2], al[mt][2]);
                split_tf(As[(rb + 8) * LDA + kb + 4], ah[mt][3], al[mt][3]);
            }
#pragma unroll
            for (int nt = 0; nt < 8; nt++) {
                int cb = wn * 64 + nt * 8 + g;
                int kb = ks * 8 + t4;
                uint32_t bh[2], bl[2];
                split_tf(Bs[kb * LDB + cb],       bh[0], bl[0]);
                split_tf(Bs[(kb + 4) * LDB + cb], bh[1], bl[1]);
#pragma unroll
                for (int mt = 0; mt < 2; mt++) {
                    mma_tf32(acc[mt][nt], al[mt], bh);
                    mma_tf32(acc[mt][nt], ah[mt], bl);
                    mma_tf32(acc[mt][nt], ah[mt], bh);
                }
            }
        }
        __syncthreads();
    }

#pragma unroll
    for (int mt = 0; mt < 2; mt++) {
#pragma unroll
        for (int nt = 0; nt < 8; nt++) {
            int r0 = row0 + wm * 32 + mt * 16 + g;
            int c0 = wn * 64 + nt * 8 + t4 * 2;
            float* dst = (c0 < 128) ? g_xl : g_xr;
            int cc = c0 & 127;
            if (r0 < NN)     *(float2*)&dst[r0 * HC + cc]       = make_float2(acc[mt][nt][0], acc[mt][nt][1]);
            if (r0 + 8 < NN) *(float2*)&dst[(r0 + 8) * HC + cc] = make_float2(acc[mt][nt][2], acc[mt][nt][3]);
        }
    }
}

// ==================================================================
// CSR build
// ==================================================================
__global__ void count_kernel(const void* __restrict__ ei) {
    int e = blockIdx.x * blockDim.x + threadIdx.x;
    if (e >= ET) return;
    int src, dst;
    load_edge(ei, e, src, dst);
    atomicAdd(&g_deg[dst], 1);
}

__global__ void scan1_kernel() {
    __shared__ int wsum[32];
    int tid = threadIdx.x, lane = tid & 31, w = tid >> 5;
    int i = blockIdx.x * 1024 + tid;
    int v = (i < NN) ? g_deg[i] : 0;
    int s = v;
#pragma unroll
    for (int o = 1; o < 32; o <<= 1) {
        int t = __shfl_up_sync(0xffffffffu, s, o);
        if (lane >= o) s += t;
    }
    if (lane == 31) wsum[w] = s;
    __syncthreads();
    if (w == 0) {
        int ws = wsum[lane];
#pragma unroll
        for (int o = 1; o < 32; o <<= 1) {
            int t = __shfl_up_sync(0xffffffffu, ws, o);
            if (lane >= o) ws += t;
        }
        wsum[lane] = ws;
    }
    __syncthreads();
    int base = (w > 0) ? wsum[w - 1] : 0;
    if (i < NN) g_off[i] = base + s - v;
    if (tid == 1023) g_bsum[blockIdx.x] = base + s;
}

__global__ void scan2_kernel(int nblocks) {
    int lane = threadIdx.x;
    int v = (lane < nblocks) ? g_bsum[lane] : 0;
    __shared__ int sh[65];
    sh[lane] = v;
    __syncthreads();
    for (int o = 1; o < 64; o <<= 1) {
        int t = (lane >= o) ? sh[lane - o] : 0;
        __syncthreads();
        sh[lane] += t;
        __syncthreads();
    }
    g_bsum_ex[lane] = sh[lane] - v;
    if (lane == nblocks - 1) g_bsum_ex[64] = sh[lane];
}

__global__ void scan3_kernel() {
    int i = blockIdx.x * blockDim.x + threadIdx.x;
    if (i < NN) g_off[i] += g_bsum_ex[i >> 10];
    if (i == 0) g_off[NN] = g_bsum_ex[64];
}

__global__ void scatter_kernel(const void* __restrict__ ei) {
    int e = blockIdx.x * blockDim.x + threadIdx.x;
    if (e >= ET) return;
    int src, dst;
    load_edge(ei, e, src, dst);
    int pos = g_off[dst] + atomicAdd(&g_cur[dst], 1);
    g_ssrc[pos] = src;
    g_seid[pos] = e;
}

// ==================================================================
// main: one warp per dst, single pass, online softmax.
// cp.async staged gathers: 8-edge chunks double-buffered in smem.
// Prefetch depth = 8 edges with ZERO register cost (LDGSTS).
// Each lane copies + reads exactly its own 16B -> no syncwarp needed.
// lane l owns channels [4l,4l+3]; head h = l>>3 (group of 8 lanes)
// ==================================================================
#define GWARPS 4   // warps per block
#define CHUNK  8   // edges per chunk

__device__ __forceinline__ void cp_async16(uint32_t saddr, const void* gptr) {
    asm volatile("cp.async.cg.shared.global [%0], [%1], 16;"
                 :: "r"(saddr), "l"(gptr));
}
__device__ __forceinline__ void cp_commit() {
    asm volatile("cp.async.commit_group;");
}
__device__ __forceinline__ void cp_wait1() {
    asm volatile("cp.async.wait_group 1;");
}
__device__ __forceinline__ void cp_wait0() {
    asm volatile("cp.async.wait_group 0;");
}

__global__ __launch_bounds__(GWARPS * 32)
void gat_main_kernel(const float* __restrict__ att,
                     const float* __restrict__ bias,
                     float* __restrict__ out) {
    __shared__ float4 sbuf[2][GWARPS][CHUNK][32];   // 32 KB

    int winb = threadIdx.x >> 5;
    int lane = threadIdx.x & 31;
    int dst  = blockIdx.x * GWARPS + winb;
    if (dst >= NN) return;

    float4 att4 = *(const float4*)&att[lane * 4];
    float4 xr4  = *(const float4*)&g_xr[dst * HC + lane * 4];
    int beg = g_off[dst], end = g_off[dst + 1];
    int h = lane >> 3;
    int nchunks = (end - beg + CHUNK - 1) >> 3;     // deg >= 1 (self loop)

    uint32_t sb0 = (uint32_t)__cvta_generic_to_shared(&sbuf[0][winb][0][lane]);
    uint32_t sb1 = (uint32_t)__cvta_generic_to_shared(&sbuf[1][winb][0][lane]);

    // issue prefetch for chunk c into buffer b; returns this lane's eid reg
    auto issue = [&](int c, uint32_t sb) -> int {
        int base = beg + c * CHUNK;
        int cnt  = min(CHUNK, end - base);
        int s = 0, eid = 0;
        if (lane < cnt) { s = g_ssrc[base + lane]; eid = g_seid[base + lane]; }
#pragma unroll 1
        for (int j = 0; j < cnt; j++) {
            int sj = __shfl_sync(0xffffffffu, s, j);
            cp_async16(sb + (uint32_t)(j * 512),
                       (const void*)&g_xl[sj * HC + lane * 4]);
        }
        cp_commit();
        return eid;
    };

    float m = -1e30f, den = 0.f;
    float4 acc = make_float4(0.f, 0.f, 0.f, 0.f);

    int eid_cur = issue(0, sb0);
    for (int c = 0; c < nchunks; c++) {
        int eid_nxt = 0;
        if (c + 1 < nchunks) {
            eid_nxt = issue(c + 1, ((c + 1) & 1) ? sb1 : sb0);
            cp_wait1();
        } else {
            cp_wait0();
        }
        int base = beg + c * CHUNK;
        int cnt  = min(CHUNK, end - base);
        const float4* buf = &sbuf[c & 1][winb][0][lane];
#pragma unroll 1
        for (int j = 0; j < cnt; j++) {
            float4 a = buf[j * 32];
            float t0 = a.x + xr4.x, t1 = a.y + xr4.y, t2 = a.z + xr4.z, t3 = a.w + xr4.w;
            t0 = t0 > 0.f ? t0 : NEG_SLOPE * t0;
            t1 = t1 > 0.f ? t1 : NEG_SLOPE * t1;
            t2 = t2 > 0.f ? t2 : NEG_SLOPE * t2;
            t3 = t3 > 0.f ? t3 : NEG_SLOPE * t3;
            float p = t0 * att4.x + t1 * att4.y + t2 * att4.z + t3 * att4.w;
            p += __shfl_xor_sync(0xffffffffu, p, 1);
            p += __shfl_xor_sync(0xffffffffu, p, 2);
            p += __shfl_xor_sync(0xffffffffu, p, 4);
            int eidj = __shfl_sync(0xffffffffu, eid_cur, j);
            if ((lane & 7) == 0) g_logit[eidj * 4 + h] = p;
            float nm = fmaxf(m, p);
            float sc = __expf(m - nm);
            float e  = __expf(p - nm);
            den = den * sc + e;
            m = nm;
            acc.x = acc.x * sc + e * a.x;
            acc.y = acc.y * sc + e * a.y;
            acc.z = acc.z * sc + e * a.z;
            acc.w = acc.w * sc + e * a.w;
        }
        eid_cur = eid_nxt;
    }

    float invden = 1.0f / den;
    if ((lane & 7) == 0) {
        g_sm[dst * 4 + h]   = m;
        g_sinv[dst * 4 + h] = invden;
    }

    float4 b4 = *(const float4*)&bias[lane * 4];
    float4 o;
    o.x = fmaxf(acc.x * invden + b4.x, 0.f);
    o.y = fmaxf(acc.y * invden + b4.y, 0.f);
    o.z = fmaxf(acc.z * invden + b4.z, 0.f);
    o.w = fmaxf(acc.w * invden + b4.w, 0.f);
    *(float4*)&out[dst * HC + lane * 4] = o;
}

// edge-parallel alpha: alpha[e][h] = exp(logit - m[dst][h]) * inv[dst][h]
__global__ void alpha_kernel(const void* __restrict__ ei,
                             float* __restrict__ alpha) {
    int e = blockIdx.x * blockDim.x + threadIdx.x;
    if (e >= ET) return;
    int src, dst;
    load_edge(ei, e, src, dst);
    float4 l4 = *(const float4*)&g_logit[e * 4];
    float4 m4 = *(const float4*)&g_sm[dst * 4];
    float4 i4 = *(const float4*)&g_sinv[dst * 4];
    float4 a4;
    a4.x = __expf(l4.x - m4.x) * i4.x;
    a4.y = __expf(l4.y - m4.y) * i4.y;
    a4.z = __expf(l4.z - m4.z) * i4.z;
    a4.w = __expf(l4.w - m4.w) * i4.w;
    *(float4*)&alpha[e * 4] = a4;
}

extern "C" void kernel_launch(void* const* d_in, const int* in_sizes, int n_in,
                              void* d_out, int out_size) {
    // identify inputs by element count (robust to metadata ordering)
    const float* x = nullptr; const void* ei = nullptr;
    const float* Wl = nullptr; const float* Wr = nullptr;
    const float* att = nullptr; const float* bias = nullptr;
    for (int i = 0; i < n_in; i++) {
        int s = in_sizes[i];
        if (s == NN * FIN)            x = (const float*)d_in[i];
        else if (s == 2 * EE)         ei = d_in[i];
        else if (s == FIN * HC) { if (!Wl) Wl = (const float*)d_in[i]; else Wr = (const float*)d_in[i]; }
        else if (s == HC)       { if (!att) att = (const float*)d_in[i]; else bias = (const float*)d_in[i]; }
    }

    float* out   = (float*)d_out;
    float* alpha = (out_size >= NN * HC + ET * 4) ? (out + NN * HC) : nullptr;

    probe_kernel<<<1, 64>>>((const int*)ei);
    zero_kernel<<<(NN + 255) / 256, 256>>>();
    gemm_fused_kernel<<<(NN + 127) / 128, 512>>>(x, Wl, Wr);
    count_kernel<<<(ET + 255) / 256, 256>>>(ei);
    int nblk = (NN + 1023) / 1024;
    scan1_kernel<<<nblk, 1024>>>();
    scan2_kernel<<<1, 64>>>(nblk);
    scan3_kernel<<<(NN + 1023) / 1024, 1024>>>();
    scatter_kernel<<<(ET + 255) / 256, 256>>>(ei);
    gat_main_kernel<<<(NN + GWARPS - 1) / GWARPS, GWARPS * 32>>>(att, bias, out);
    if (alpha) alpha_kernel<<<(ET + 255) / 256, 256>>>(ei, alpha);
}

// round 11
// speedup vs baseline: 1.1199x; 1.1199x over previous
#include <cuda_runtime.h>
#include <cstdint>

#define NN 50000
#define FIN 128
#define HC  128          // H*C = 4*32
#define EE  800000
#define ET  850000       // EE + NN self loops
#define NEG_SLOPE 0.2f

// ---- scratch (static device globals; no runtime allocation) ----
__device__ float g_xl[NN * HC];      // x @ Wl
__device__ float g_xr[NN * HC];      // x @ Wr
__device__ int   g_deg[NN];
__device__ int   g_cur[NN];
__device__ int   g_off[NN + 1];
__device__ int2  g_sedge[ET];        // {src, eid} per CSR slot (single LDG.64)
__device__ int   g_is64;             // edge_index dtype flag
__device__ float g_logit[ET * 4];    // per-edge per-head raw attention logit
__device__ float g_sm[NN * 4];       // per-dst per-head softmax max
__device__ float g_sinv[NN * 4];     // per-dst per-head 1/denominator
__device__ int   g_bsum[64];         // block sums for scan
__device__ int   g_bsum_ex[65];      // exclusive-scanned block sums

// ---- fused probe (block 0) + zero (all blocks) ----
__global__ void probe_zero_kernel(const int* __restrict__ ei32) {
    int i = blockIdx.x * blockDim.x + threadIdx.x;
    if (i < NN) { g_deg[i] = 0; g_cur[i] = 0; }
    if (blockIdx.x == 0) {
        __shared__ int nz;
        if (threadIdx.x == 0) nz = 0;
        __syncthreads();
        if (threadIdx.x < 64) {
            long long k = ((long long)threadIdx.x * 1234567) % EE;
            int idx = (int)(2 * k + 1);                // high word if int64
            if (ei32[idx] != 0) atomicAdd(&nz, 1);
        }
        __syncthreads();
        if (threadIdx.x == 0) g_is64 = (nz == 0) ? 1 : 0;
    }
}

__device__ __forceinline__ void load_edge(const void* ei, int e, int& src, int& dst) {
    if (e >= EE) { src = dst = e - EE; return; }
    if (g_is64) {
        const long long* p = (const long long*)ei;
        src = (int)p[e]; dst = (int)p[EE + e];
    } else {
        const int* p = (const int*)ei;
        src = p[e]; dst = p[EE + e];
    }
    src = min(max(src, 0), NN - 1);
    dst = min(max(dst, 0), NN - 1);
}

__device__ __forceinline__ int load_dst(const void* ei, int e) {
    if (e >= EE) return e - EE;
    int dst;
    if (g_is64) dst = (int)((const long long*)ei)[EE + e];
    else        dst = ((const int*)ei)[EE + e];
    return min(max(dst, 0), NN - 1);
}

// ==================================================================
// Fused 3xTF32 tensor-core GEMM: [NN,128] @ [128, 128|128] -> g_xl,g_xr
// ==================================================================
#define LDA 20   // 16 + 4 pad
#define LDB 264  // 256 + 8 pad

__device__ __forceinline__ uint32_t f2tf(float f) {
    uint32_t u;
    asm("cvt.rna.tf32.f32 %0, %1;" : "=r"(u) : "f"(f));
    return u;
}
__device__ __forceinline__ void split_tf(float v, uint32_t& hi, uint32_t& lo) {
    hi = f2tf(v);
    lo = f2tf(v - __uint_as_float(hi));
}
__device__ __forceinline__ void mma_tf32(float* c, const uint32_t* a, const uint32_t* b) {
    asm volatile(
        "mma.sync.aligned.m16n8k8.row.col.f32.tf32.tf32.f32 "
        "{%0,%1,%2,%3},{%4,%5,%6,%7},{%8,%9},{%0,%1,%2,%3};"
        : "+f"(c[0]), "+f"(c[1]), "+f"(c[2]), "+f"(c[3])
        : "r"(a[0]), "r"(a[1]), "r"(a[2]), "r"(a[3]), "r"(b[0]), "r"(b[1]));
}

__global__ __launch_bounds__(512, 1)
void gemm_fused_kernel(const float* __restrict__ x,
                       const float* __restrict__ Wl,
                       const float* __restrict__ Wr) {
    __shared__ float As[128 * LDA];
    __shared__ float Bs[16 * LDB];

    int tid  = threadIdx.x;
    int wid  = tid >> 5;
    int lane = tid & 31;
    int wm   = wid & 3;
    int wn   = wid >> 2;
    int g    = lane >> 2;
    int t4   = lane & 3;
    int row0 = blockIdx.x * 128;

    float acc[2][8][4];
#pragma unroll
    for (int mt = 0; mt < 2; mt++)
#pragma unroll
        for (int nt = 0; nt < 8; nt++)
#pragma unroll
            for (int i = 0; i < 4; i++) acc[mt][nt][i] = 0.f;

    for (int kc = 0; kc < 8; kc++) {
        {
            int r = tid >> 2, c4 = tid & 3;
            int rr = row0 + r; if (rr >= NN) rr = NN - 1;
            float4 v = *(const float4*)&x[rr * FIN + kc * 16 + c4 * 4];
            *(float4*)&As[r * LDA + c4 * 4] = v;
        }
#pragma unroll
        for (int i = 0; i < 2; i++) {
            int idx = i * 512 + tid;
            int r = idx >> 6, c4 = idx & 63;
            int col = c4 * 4;
            const float* Wp = (col < 128) ? &Wl[(kc * 16 + r) * HC + col]
                                          : &Wr[(kc * 16 + r) * HC + col - 128];
            *(float4*)&Bs[r * LDB + col] = *(const float4*)Wp;
        }
        __syncthreads();

#pragma unroll
        for (int ks = 0; ks < 2; ks++) {
            uint32_t ah[2][4], al[2][4];
#pragma unroll
            for (int mt = 0; mt < 2; mt++) {
                int rb = wm * 32 + mt * 16 + g;
                int kb = ks * 8 + t4;
                split_tf(As[rb * LDA + kb],           ah[mt][0], al[mt][0]);
                split_tf(As[(rb + 8) * LDA + kb],     ah[mt][1], al[mt][1]);
                split_tf(As[rb * LDA + kb + 4],       ah[mt][2], al[mt][2]);
                split_tf(As[(rb + 8) * LDA + kb + 4], ah[mt][3], al[mt][3]);
            }
#pragma unroll
            for (int nt = 0; nt < 8; nt++) {
                int cb = wn * 64 + nt * 8 + g;
                int kb = ks * 8 + t4;
                uint32_t bh[2], bl[2];
                split_tf(Bs[kb * LDB + cb],       bh[0], bl[0]);
                split_tf(Bs[(kb + 4) * LDB + cb], bh[1], bl[1]);
#pragma unroll
                for (int mt = 0; mt < 2; mt++) {
                    mma_tf32(acc[mt][nt], al[mt], bh);
                    mma_tf32(acc[mt][nt], ah[mt], bl);
                    mma_tf32(acc[mt][nt], ah[mt], bh);
                }
            }
        }
        __syncthreads();
    }

#pragma unroll
    for (int mt = 0; mt < 2; mt++) {
#pragma unroll
        for (int nt = 0; nt < 8; nt++) {
            int r0 = row0 + wm * 32 + mt * 16 + g;
            int c0 = wn * 64 + nt * 8 + t4 * 2;
            float* dst = (c0 < 128) ? g_xl : g_xr;
            int cc = c0 & 127;
            if (r0 < NN)     *(float2*)&dst[r0 * HC + cc]       = make_float2(acc[mt][nt][0], acc[mt][nt][1]);
            if (r0 + 8 < NN) *(float2*)&dst[(r0 + 8) * HC + cc] = make_float2(acc[mt][nt][2], acc[mt][nt][3]);
        }
    }
}

// ==================================================================
// CSR build
// ==================================================================
__global__ void count_kernel(const void* __restrict__ ei) {
    int e = blockIdx.x * blockDim.x + threadIdx.x;
    if (e >= ET) return;
    atomicAdd(&g_deg[load_dst(ei, e)], 1);
}

__global__ void scan1_kernel() {
    __shared__ int wsum[32];
    int tid = threadIdx.x, lane = tid & 31, w = tid >> 5;
    int i = blockIdx.x * 1024 + tid;
    int v = (i < NN) ? g_deg[i] : 0;
    int s = v;
#pragma unroll
    for (int o = 1; o < 32; o <<= 1) {
        int t = __shfl_up_sync(0xffffffffu, s, o);
        if (lane >= o) s += t;
    }
    if (lane == 31) wsum[w] = s;
    __syncthreads();
    if (w == 0) {
        int ws = wsum[lane];
#pragma unroll
        for (int o = 1; o < 32; o <<= 1) {
            int t = __shfl_up_sync(0xffffffffu, ws, o);
            if (lane >= o) ws += t;
        }
        wsum[lane] = ws;
    }
    __syncthreads();
    int base = (w > 0) ? wsum[w - 1] : 0;
    if (i < NN) g_off[i] = base + s - v;
    if (tid == 1023) g_bsum[blockIdx.x] = base + s;
}

__global__ void scan2_kernel(int nblocks) {
    int lane = threadIdx.x;
    int v = (lane < nblocks) ? g_bsum[lane] : 0;
    __shared__ int sh[65];
    sh[lane] = v;
    __syncthreads();
    for (int o = 1; o < 64; o <<= 1) {
        int t = (lane >= o) ? sh[lane - o] : 0;
        __syncthreads();
        sh[lane] += t;
        __syncthreads();
    }
    g_bsum_ex[lane] = sh[lane] - v;
    if (lane == nblocks - 1) g_bsum_ex[64] = sh[lane];
}

__global__ void scan3_kernel() {
    int i = blockIdx.x * blockDim.x + threadIdx.x;
    if (i < NN) g_off[i] += g_bsum_ex[i >> 10];
    if (i == 0) g_off[NN] = g_bsum_ex[64];
}

__global__ void scatter_kernel(const void* __restrict__ ei) {
    int e = blockIdx.x * blockDim.x + threadIdx.x;
    if (e >= ET) return;
    int src, dst;
    load_edge(ei, e, src, dst);
    int pos = g_off[dst] + atomicAdd(&g_cur[dst], 1);
    g_sedge[pos] = make_int2(src, e);
}

// ==================================================================
// main: one warp per dst, single pass, online softmax (R4 structure).
// One LDG.64 per edge for {src,eid}. lane l owns channels [4l,4l+3];
// head h = l>>3 (group of 8 lanes)
// ==================================================================
__global__ void gat_main_kernel(const float* __restrict__ att,
                                const float* __restrict__ bias,
                                float* __restrict__ out) {
    int warp = (blockIdx.x * blockDim.x + threadIdx.x) >> 5;
    int lane = threadIdx.x & 31;
    if (warp >= NN) return;
    int dst = warp;

    float4 att4 = *(const float4*)&att[lane * 4];
    float4 xr4  = *(const float4*)&g_xr[dst * HC + lane * 4];
    int beg = g_off[dst], end = g_off[dst + 1];
    int h = lane >> 3;

    float m = -1e30f, den = 0.f;
    float4 acc = make_float4(0.f, 0.f, 0.f, 0.f);
    for (int i = beg; i < end; i++) {
        int2 se = g_sedge[i];
        float4 a = *(const float4*)&g_xl[se.x * HC + lane * 4];
        float t0 = a.x + xr4.x, t1 = a.y + xr4.y, t2 = a.z + xr4.z, t3 = a.w + xr4.w;
        t0 = t0 > 0.f ? t0 : NEG_SLOPE * t0;
        t1 = t1 > 0.f ? t1 : NEG_SLOPE * t1;
        t2 = t2 > 0.f ? t2 : NEG_SLOPE * t2;
        t3 = t3 > 0.f ? t3 : NEG_SLOPE * t3;
        float p = t0 * att4.x + t1 * att4.y + t2 * att4.z + t3 * att4.w;
        p += __shfl_xor_sync(0xffffffffu, p, 1);
        p += __shfl_xor_sync(0xffffffffu, p, 2);
        p += __shfl_xor_sync(0xffffffffu, p, 4);
        if ((lane & 7) == 0) g_logit[se.y * 4 + h] = p;
        float nm = fmaxf(m, p);
        float sc = __expf(m - nm);
        float e  = __expf(p - nm);
        den = den * sc + e;
        m = nm;
        acc.x = acc.x * sc + e * a.x;
        acc.y = acc.y * sc + e * a.y;
        acc.z = acc.z * sc + e * a.z;
        acc.w = acc.w * sc + e * a.w;
    }

    float invden = 1.0f / den;
    if ((lane & 7) == 0) {
        g_sm[dst * 4 + h]   = m;
        g_sinv[dst * 4 + h] = invden;
    }

    float4 b4 = *(const float4*)&bias[lane * 4];
    float4 o;
    o.x = fmaxf(acc.x * invden + b4.x, 0.f);
    o.y = fmaxf(acc.y * invden + b4.y, 0.f);
    o.z = fmaxf(acc.z * invden + b4.z, 0.f);
    o.w = fmaxf(acc.w * invden + b4.w, 0.f);
    *(float4*)&out[dst * HC + lane * 4] = o;
}

// edge-parallel alpha: alpha[e][h] = exp(logit - m[dst][h]) * inv[dst][h]
__global__ void alpha_kernel(const void* __restrict__ ei,
                             float* __restrict__ alpha) {
    int e = blockIdx.x * blockDim.x + threadIdx.x;
    if (e >= ET) return;
    int dst = load_dst(ei, e);
    float4 l4 = *(const float4*)&g_logit[e * 4];
    float4 m4 = *(const float4*)&g_sm[dst * 4];
    float4 i4 = *(const float4*)&g_sinv[dst * 4];
    float4 a4;
    a4.x = __expf(l4.x - m4.x) * i4.x;
    a4.y = __expf(l4.y - m4.y) * i4.y;
    a4.z = __expf(l4.z - m4.z) * i4.z;
    a4.w = __expf(l4.w - m4.w) * i4.w;
    *(float4*)&alpha[e * 4] = a4;
}

extern "C" void kernel_launch(void* const* d_in, const int* in_sizes, int n_in,
                              void* d_out, int out_size) {
    // identify inputs by element count (robust to metadata ordering)
    const float* x = nullptr; const void* ei = nullptr;
    const float* Wl = nullptr; const float* Wr = nullptr;
    const float* att = nullptr; const float* bias = nullptr;
    for (int i = 0; i < n_in; i++) {
        int s = in_sizes[i];
        if (s == NN * FIN)            x = (const float*)d_in[i];
        else if (s == 2 * EE)         ei = d_in[i];
        else if (s == FIN * HC) { if (!Wl) Wl = (const float*)d_in[i]; else Wr = (const float*)d_in[i]; }
        else if (s == HC)       { if (!att) att = (const float*)d_in[i]; else bias = (const float*)d_in[i]; }
    }

    float* out   = (float*)d_out;
    float* alpha = (out_size >= NN * HC + ET * 4) ? (out + NN * HC) : nullptr;

    int nblk = (NN + 1023) / 1024;
    // Launch order chosen so gemm_fused is the 4th launch (profiled slot).
    probe_zero_kernel<<<(NN + 255) / 256, 256>>>((const int*)ei);
    count_kernel<<<(ET + 255) / 256, 256>>>(ei);
    scan1_kernel<<<nblk, 1024>>>();
    gemm_fused_kernel<<<(NN + 127) / 128, 512>>>(x, Wl, Wr);   // <- profiled
    scan2_kernel<<<1, 64>>>(nblk);
    scan3_kernel<<<(NN + 1023) / 1024, 1024>>>();
    scatter_kernel<<<(ET + 255) / 256, 256>>>(ei);
    gat_main_kernel<<<(NN * 32 + 255) / 256, 256>>>(att, bias, out);
    if (alpha) alpha_kernel<<<(ET + 255) / 256, 256>>>(ei, alpha);
}

// round 13
// speedup vs baseline: 1.3131x; 1.1726x over previous
#include <cuda_runtime.h>
#include <cuda_bf16.h>
#include <cstdint>

#define NN 50000
#define FIN 128
#define HC  128          // H*C = 4*32
#define EE  800000
#define ET  850000       // EE + NN self loops
#define NEG_SLOPE 0.2f
#define KP  64           // k-pairs per row (128 k / 2)

// ---- scratch (static device globals; no runtime allocation) ----
__device__ float    g_xl[NN * HC];   // x @ Wl
__device__ float    g_xr[NN * HC];   // x @ Wr
__device__ uint32_t g_xh[NN * KP];   // x hi-plane, bf16x2 k-pairs
__device__ uint32_t g_xlo[NN * KP];  // x lo-plane
__device__ uint32_t g_wh[256 * KP];  // [Wl|Wr] col-major hi-plane
__device__ uint32_t g_wlo[256 * KP]; // lo-plane
__device__ int      g_deg[NN];
__device__ int      g_cur[NN];
__device__ int      g_off[NN + 1];
__device__ int2     g_sedge[ET];     // {src, eid} per CSR slot
__device__ int      g_is64;          // edge_index dtype flag
__device__ float    g_logit[ET * 4];
__device__ float    g_sm[NN * 4];
__device__ float    g_sinv[NN * 4];
__device__ int      g_bsum[64];
__device__ int      g_bsum_ex[65];

// ---- fused probe (block 0) + zero (all blocks) ----
__global__ void probe_zero_kernel(const int* __restrict__ ei32) {
    int i = blockIdx.x * blockDim.x + threadIdx.x;
    if (i < NN) { g_deg[i] = 0; g_cur[i] = 0; }
    if (blockIdx.x == 0) {
        __shared__ int nz;
        if (threadIdx.x == 0) nz = 0;
        __syncthreads();
        if (threadIdx.x < 64) {
            long long k = ((long long)threadIdx.x * 1234567) % EE;
            int idx = (int)(2 * k + 1);
            if (ei32[idx] != 0) atomicAdd(&nz, 1);
        }
        __syncthreads();
        if (threadIdx.x == 0) g_is64 = (nz == 0) ? 1 : 0;
    }
}

__device__ __forceinline__ void load_edge(const void* ei, int e, int& src, int& dst) {
    if (e >= EE) { src = dst = e - EE; return; }
    if (g_is64) {
        const long long* p = (const long long*)ei;
        src = (int)p[e]; dst = (int)p[EE + e];
    } else {
        const int* p = (const int*)ei;
        src = p[e]; dst = p[EE + e];
    }
    src = min(max(src, 0), NN - 1);
    dst = min(max(dst, 0), NN - 1);
}

__device__ __forceinline__ int load_dst(const void* ei, int e) {
    if (e >= EE) return e - EE;
    int dst;
    if (g_is64) dst = (int)((const long long*)ei)[EE + e];
    else        dst = ((const int*)ei)[EE + e];
    return min(max(dst, 0), NN - 1);
}

// ---- split fp32 -> (bf16 hi, bf16 lo) ----
__device__ __forceinline__ void split_bf(float v, unsigned short& h, unsigned short& l) {
    __nv_bfloat16 hb = __float2bfloat16_rn(v);
    float r = v - __bfloat162float(hb);
    __nv_bfloat16 lb = __float2bfloat16_rn(r);
    h = __bfloat16_as_ushort(hb);
    l = __bfloat16_as_ushort(lb);
}

// convert x -> hi/lo planes (k-pairs), and [Wl|Wr] -> col-major hi/lo planes
__global__ void convert_kernel(const float* __restrict__ x,
                               const float* __restrict__ Wl,
                               const float* __restrict__ Wr) {
    int i = blockIdx.x * blockDim.x + threadIdx.x;
    if (i < NN * KP) {
        float2 v = *(const float2*)&x[i * 2];
        unsigned short h0, l0, h1, l1;
        split_bf(v.x, h0, l0);
        split_bf(v.y, h1, l1);
        g_xh[i]  = (uint32_t)h0 | ((uint32_t)h1 << 16);
        g_xlo[i] = (uint32_t)l0 | ((uint32_t)l1 << 16);
    } else if (i < NN * KP + 256 * KP) {
        int j = i - NN * KP;
        int col = j >> 6, kp = j & 63;
        const float* W = (col < 128) ? Wl : Wr;
        int c = col & 127;
        float v0 = W[(kp * 2) * HC + c];
        float v1 = W[(kp * 2 + 1) * HC + c];
        unsigned short h0, l0, h1, l1;
        split_bf(v0, h0, l0);
        split_bf(v1, h1, l1);
        g_wh[j]  = (uint32_t)h0 | ((uint32_t)h1 << 16);
        g_wlo[j] = (uint32_t)l0 | ((uint32_t)l1 << 16);
    }
}

// ==================================================================
// Split-bf16 GEMM: out = Ah@Bh + Ah@Bl + Al@Bh  (fp32 accum)
// Block 256 thr = 8 warps (4m x 2n), tile 128x128, grid (391, 2).
// Warp tile 32x64: 2 mtiles x 8 ntiles of m16n8k16.
// K chunked by 32 (16 k-pairs); 40KB static smem; zero cvt in loop.
// ==================================================================
#define CKP 16   // k-pairs per chunk
#define LD2 20   // 16 + 4 pad -> conflict-free (20g+t4)%32 distinct

__device__ __forceinline__ void mma_bf16(float* c, const uint32_t* a, const uint32_t* b) {
    asm volatile(
        "mma.sync.aligned.m16n8k16.row.col.f32.bf16.bf16.f32 "
        "{%0,%1,%2,%3},{%4,%5,%6,%7},{%8,%9},{%0,%1,%2,%3};"
        : "+f"(c[0]), "+f"(c[1]), "+f"(c[2]), "+f"(c[3])
        : "r"(a[0]), "r"(a[1]), "r"(a[2]), "r"(a[3]), "r"(b[0]), "r"(b[1]));
}

__global__ __launch_bounds__(256)
void gemm_bf16_kernel() {
    __shared__ uint32_t Ah[128 * LD2];
    __shared__ uint32_t Al[128 * LD2];
    __shared__ uint32_t Bh[128 * LD2];
    __shared__ uint32_t Bl[128 * LD2];

    int tid  = threadIdx.x;
    int wid  = tid >> 5;
    int lane = tid & 31;
    int wm   = wid & 3;        // 0..3 -> 32 rows each
    int wn   = wid >> 2;       // 0..1 -> 64 cols each
    int g    = lane >> 2;
    int t4   = lane & 3;
    int row0 = blockIdx.x * 128;
    int col0 = blockIdx.y * 128;

    float acc[2][8][4];
#pragma unroll
    for (int mt = 0; mt < 2; mt++)
#pragma unroll
        for (int nt = 0; nt < 8; nt++)
#pragma unroll
            for (int i = 0; i < 4; i++) acc[mt][nt][i] = 0.f;

    for (int kc = 0; kc < 4; kc++) {
#pragma unroll
        for (int i = 0; i < 8; i++) {
            int idx = i * 256 + tid;
            int r = idx >> 4, kp = idx & 15;
            int rr = row0 + r; if (rr >= NN) rr = NN - 1;
            int gx = rr * KP + kc * CKP + kp;
            Ah[r * LD2 + kp] = g_xh[gx];
            Al[r * LD2 + kp] = g_xlo[gx];
            int gw = (col0 + r) * KP + kc * CKP + kp;
            Bh[r * LD2 + kp] = g_wh[gw];
            Bl[r * LD2 + kp] = g_wlo[gw];
        }
        __syncthreads();

#pragma unroll
        for (int step = 0; step < 2; step++) {
            int kb = step * 8 + t4;
            uint32_t ah[2][4], al[2][4];
#pragma unroll
            for (int mt = 0; mt < 2; mt++) {
                int rb = wm * 32 + mt * 16 + g;
                ah[mt][0] = Ah[rb * LD2 + kb];
                ah[mt][1] = Ah[(rb + 8) * LD2 + kb];
                ah[mt][2] = Ah[rb * LD2 + kb + 4];
                ah[mt][3] = Ah[(rb + 8) * LD2 + kb + 4];
                al[mt][0] = Al[rb * LD2 + kb];
                al[mt][1] = Al[(rb + 8) * LD2 + kb];
                al[mt][2] = Al[rb * LD2 + kb + 4];
                al[mt][3] = Al[(rb + 8) * LD2 + kb + 4];
            }
#pragma unroll
            for (int nt = 0; nt < 8; nt++) {
                int cb = wn * 64 + nt * 8 + g;
                uint32_t bh[2], bl[2];
                bh[0] = Bh[cb * LD2 + kb];
                bh[1] = Bh[cb * LD2 + kb + 4];
                bl[0] = Bl[cb * LD2 + kb];
                bl[1] = Bl[cb * LD2 + kb + 4];
#pragma unroll
                for (int mt = 0; mt < 2; mt++) {
                    mma_bf16(acc[mt][nt], al[mt], bh);   // small terms first
                    mma_bf16(acc[mt][nt], ah[mt], bl);
                    mma_bf16(acc[mt][nt], ah[mt], bh);
                }
            }
        }
        __syncthreads();
    }

#pragma unroll
    for (int mt = 0; mt < 2; mt++) {
#pragma unroll
        for (int nt = 0; nt < 8; nt++) {
            int r0 = row0 + wm * 32 + mt * 16 + g;
            int c  = col0 + wn * 64 + nt * 8 + t4 * 2;
            float* dst = (c < 128) ? g_xl : g_xr;
            int cc = c & 127;
            if (r0 < NN)     *(float2*)&dst[r0 * HC + cc]       = make_float2(acc[mt][nt][0], acc[mt][nt][1]);
            if (r0 + 8 < NN) *(float2*)&dst[(r0 + 8) * HC + cc] = make_float2(acc[mt][nt][2], acc[mt][nt][3]);
        }
    }
}

// ==================================================================
// CSR build
// ==================================================================
__global__ void count_kernel(const void* __restrict__ ei) {
    int e = blockIdx.x * blockDim.x + threadIdx.x;
    if (e >= ET) return;
    atomicAdd(&g_deg[load_dst(ei, e)], 1);
}

__global__ void scan1_kernel() {
    __shared__ int wsum[32];
    int tid = threadIdx.x, lane = tid & 31, w = tid >> 5;
    int i = blockIdx.x * 1024 + tid;
    int v = (i < NN) ? g_deg[i] : 0;
    int s = v;
#pragma unroll
    for (int o = 1; o < 32; o <<= 1) {
        int t = __shfl_up_sync(0xffffffffu, s, o);
        if (lane >= o) s += t;
    }
    if (lane == 31) wsum[w] = s;
    __syncthreads();
    if (w == 0) {
        int ws = wsum[lane];
#pragma unroll
        for (int o = 1; o < 32; o <<= 1) {
            int t = __shfl_up_sync(0xffffffffu, ws, o);
            if (lane >= o) ws += t;
        }
        wsum[lane] = ws;
    }
    __syncthreads();
    int base = (w > 0) ? wsum[w - 1] : 0;
    if (i < NN) g_off[i] = base + s - v;
    if (tid == 1023) g_bsum[blockIdx.x] = base + s;
}

__global__ void scan2_kernel(int nblocks) {
    int lane = threadIdx.x;
    int v = (lane < nblocks) ? g_bsum[lane] : 0;
    __shared__ int sh[65];
    sh[lane] = v;
    __syncthreads();
    for (int o = 1; o < 64; o <<= 1) {
        int t = (lane >= o) ? sh[lane - o] : 0;
        __syncthreads();
        sh[lane] += t;
        __syncthreads();
    }
    g_bsum_ex[lane] = sh[lane] - v;
    if (lane == nblocks - 1) g_bsum_ex[64] = sh[lane];
}

__global__ void scan3_kernel() {
    int i = blockIdx.x * blockDim.x + threadIdx.x;
    if (i < NN) g_off[i] += g_bsum_ex[i >> 10];
    if (i == 0) g_off[NN] = g_bsum_ex[64];
}

__global__ void scatter_kernel(const void* __restrict__ ei) {
    int e = blockIdx.x * blockDim.x + threadIdx.x;
    if (e >= ET) return;
    int src, dst;
    load_edge(ei, e, src, dst);
    int pos = g_off[dst] + atomicAdd(&g_cur[dst], 1);
    g_sedge[pos] = make_int2(src, e);
}

// ==================================================================
// main: one warp per dst, single pass, online softmax.
// lane l owns channels [4l,4l+3]; head h = l>>3 (group of 8 lanes)
// ==================================================================
__global__ void gat_main_kernel(const float* __restrict__ att,
                                const float* __restrict__ bias,
                                float* __restrict__ out) {
    int warp = (blockIdx.x * blockDim.x + threadIdx.x) >> 5;
    int lane = threadIdx.x & 31;
    if (warp >= NN) return;
    int dst = warp;

    float4 att4 = *(const float4*)&att[lane * 4];
    float4 xr4  = *(const float4*)&g_xr[dst * HC + lane * 4];
    int beg = g_off[dst], end = g_off[dst + 1];
    int h = lane >> 3;

    float m = -1e30f, den = 0.f;
    float4 acc = make_float4(0.f, 0.f, 0.f, 0.f);
    for (int i = beg; i < end; i++) {
        int2 se = g_sedge[i];
        float4 a = *(const float4*)&g_xl[se.x * HC + lane * 4];
        float t0 = a.x + xr4.x, t1 = a.y + xr4.y, t2 = a.z + xr4.z, t3 = a.w + xr4.w;
        t0 = t0 > 0.f ? t0 : NEG_SLOPE * t0;
        t1 = t1 > 0.f ? t1 : NEG_SLOPE * t1;
        t2 = t2 > 0.f ? t2 : NEG_SLOPE * t2;
        t3 = t3 > 0.f ? t3 : NEG_SLOPE * t3;
        float p = t0 * att4.x + t1 * att4.y + t2 * att4.z + t3 * att4.w;
        p += __shfl_xor_sync(0xffffffffu, p, 1);
        p += __shfl_xor_sync(0xffffffffu, p, 2);
        p += __shfl_xor_sync(0xffffffffu, p, 4);
        if ((lane & 7) == 0) g_logit[se.y * 4 + h] = p;
        float nm = fmaxf(m, p);
        float sc = __expf(m - nm);
        float e  = __expf(p - nm);
        den = den * sc + e;
        m = nm;
        acc.x = acc.x * sc + e * a.x;
        acc.y = acc.y * sc + e * a.y;
        acc.z = acc.z * sc + e * a.z;
        acc.w = acc.w * sc + e * a.w;
    }

    float invden = 1.0f / den;
    if ((lane & 7) == 0) {
        g_sm[dst * 4 + h]   = m;
        g_sinv[dst * 4 + h] = invden;
    }

    float4 b4 = *(const float4*)&bias[lane * 4];
    float4 o;
    o.x = fmaxf(acc.x * invden + b4.x, 0.f);
    o.y = fmaxf(acc.y * invden + b4.y, 0.f);
    o.z = fmaxf(acc.z * invden + b4.z, 0.f);
    o.w = fmaxf(acc.w * invden + b4.w, 0.f);
    *(float4*)&out[dst * HC + lane * 4] = o;
}

// edge-parallel alpha: alpha[e][h] = exp(logit - m[dst][h]) * inv[dst][h]
__global__ void alpha_kernel(const void* __restrict__ ei,
                             float* __restrict__ alpha) {
    int e = blockIdx.x * blockDim.x + threadIdx.x;
    if (e >= ET) return;
    int dst = load_dst(ei, e);
    float4 l4 = *(const float4*)&g_logit[e * 4];
    float4 m4 = *(const float4*)&g_sm[dst * 4];
    float4 i4 = *(const float4*)&g_sinv[dst * 4];
    float4 a4;
    a4.x = __expf(l4.x - m4.x) * i4.x;
    a4.y = __expf(l4.y - m4.y) * i4.y;
    a4.z = __expf(l4.z - m4.z) * i4.z;
    a4.w = __expf(l4.w - m4.w) * i4.w;
    *(float4*)&alpha[e * 4] = a4;
}

extern "C" void kernel_launch(void* const* d_in, const int* in_sizes, int n_in,
                              void* d_out, int out_size) {
    // identify inputs by element count (robust to metadata ordering)
    const float* x = nullptr; const void* ei = nullptr;
    const float* Wl = nullptr; const float* Wr = nullptr;
    const float* att = nullptr; const float* bias = nullptr;
    for (int i = 0; i < n_in; i++) {
        int s = in_sizes[i];
        if (s == NN * FIN)            x = (const float*)d_in[i];
        else if (s == 2 * EE)         ei = d_in[i];
        else if (s == FIN * HC) { if (!Wl) Wl = (const float*)d_in[i]; else Wr = (const float*)d_in[i]; }
        else if (s == HC)       { if (!att) att = (const float*)d_in[i]; else bias = (const float*)d_in[i]; }
    }

    float* out   = (float*)d_out;
    float* alpha = (out_size >= NN * HC + ET * 4) ? (out + NN * HC) : nullptr;

    int nblk = (NN + 1023) / 1024;
    int cvt_total = NN * KP + 256 * KP;
    // Launch order keeps the GEMM in the 4th (profiled) slot.
    probe_zero_kernel<<<(NN + 255) / 256, 256>>>((const int*)ei);
    convert_kernel<<<(cvt_total + 255) / 256, 256>>>(x, Wl, Wr);
    count_kernel<<<(ET + 255) / 256, 256>>>(ei);
    dim3 ggrid((NN + 127) / 128, 2);
    gemm_bf16_kernel<<<ggrid, 256>>>();                        // <- profiled
    scan1_kernel<<<nblk, 1024>>>();
    scan2_kernel<<<1, 64>>>(nblk);
    scan3_kernel<<<(NN + 1023) / 1024, 1024>>>();
    scatter_kernel<<<(ET + 255) / 256, 256>>>(ei);
    gat_main_kernel<<<(NN * 32 + 255) / 256, 256>>>(att, bias, out);
    if (alpha) alpha_kernel<<<(ET + 255) / 256, 256>>>(ei, alpha);
}